// round 16
// baseline (speedup 1.0000x reference)
#include <cuda_runtime.h>
#include <cstdint>

#define NEG_INF (-1e30f)

constexpr int B = 32;
constexpr int L = 4096;
constexpr int D = 1024;

constexpr int THREADS1 = 128;
constexpr int WARPS1 = 4;
constexpr int ROWS_PER_BLOCK = 64;
constexpr int NCHUNK = L / ROWS_PER_BLOCK;   // 64
constexpr int NPART = B * NCHUNK;            // 2048
constexpr int GRID1 = 148 * 5;               // persistent blocks (1 wave)

constexpr int P2_SPLIT = 8;                  // 128 cols per block
constexpr int THREADS2 = 256;

// Scratch (no allocations allowed in kernel_launch)
__device__ __align__(16) float g_scores[B * L];
__device__ __align__(16) float g_pacc[NPART][D];
__device__ float g_pm[NPART];
__device__ float g_pz[NPART];
__device__ int   g_next;                     // zero-init; reset in pass2

// ---- packed f32x2 helpers (PTX-only; ptxas never emits FFMA2 from C++) ----
__device__ __forceinline__ unsigned long long f2fma(unsigned long long a,
                                                    unsigned long long b,
                                                    unsigned long long c) {
    unsigned long long d;
    asm("fma.rn.f32x2 %0, %1, %2, %3;" : "=l"(d) : "l"(a), "l"(b), "l"(c));
    return d;
}
__device__ __forceinline__ unsigned long long f2mul(unsigned long long a,
                                                    unsigned long long b) {
    unsigned long long d;
    asm("mul.rn.f32x2 %0, %1, %2;" : "=l"(d) : "l"(a), "l"(b));
    return d;
}
__device__ __forceinline__ float f2sum(unsigned long long a) {
    unsigned lo, hi;
    asm("mov.b64 {%0, %1}, %2;" : "=r"(lo), "=r"(hi) : "l"(a));
    return __uint_as_float(lo) + __uint_as_float(hi);
}
__device__ __forceinline__ unsigned long long f2bcast(float f) {
    unsigned long long d;
    unsigned u = __float_as_uint(f);
    asm("mov.b64 %0, {%1, %1};" : "=l"(d) : "r"(u));
    return d;
}
// streaming (evict-first) 16B load
__device__ __forceinline__ ulonglong2 ldcs_u2(const ulonglong2* p) {
    ulonglong2 r;
    asm volatile("ld.global.cs.v2.u64 {%0, %1}, [%2];"
                 : "=l"(r.x), "=l"(r.y) : "l"(p));
    return r;
}

__global__ __launch_bounds__(THREADS1, 5)
void attn_pool_pass1(const float* __restrict__ seq,
                     const float* __restrict__ vec,
                     const int*   __restrict__ mask) {
    const int tid  = threadIdx.x;
    const int wid  = tid >> 5;
    const int lane = tid & 31;

    __shared__ int chunk_sh;
    __shared__ int row_list[ROWS_PER_BLOCK];
    __shared__ int cnt_sh[2];
    __shared__ __align__(16) float sp[2][8][4];   // [parity][row][warp]

    const unsigned b0 = lane & 1, b1 = (lane >> 1) & 1, b2 = (lane >> 2) & 1;
    const int fbase = wid * 64 + lane;   // 16-byte-unit index within a row

    for (;;) {
        // ---- steal next chunk ----
        if (tid == 0) chunk_sh = atomicAdd(&g_next, 1);
        __syncthreads();                 // also fences prior chunk's smem use
        const int blk = chunk_sh;
        if (blk >= NPART) break;
        const int b     = blk / NCHUNK;
        const int chunk = blk % NCHUNK;
        const int row0  = chunk * ROWS_PER_BLOCK;

        // ---- compaction of unmasked rows ----
        int mk = 0;
        if (tid < ROWS_PER_BLOCK)
            mk = mask[(size_t)b * L + row0 + tid];
        const unsigned bal = __ballot_sync(0xffffffffu, mk != 0);
        if (wid < 2 && lane == 0) cnt_sh[wid] = __popc(bal);
        if (tid < ROWS_PER_BLOCK && mk == 0)
            g_scores[(size_t)b * L + row0 + tid] = NEG_INF;
        __syncthreads();
        const int n_rows = cnt_sh[0] + cnt_sh[1];
        if (tid < ROWS_PER_BLOCK && mk != 0) {
            const int cbase = (wid == 1) ? cnt_sh[0] : 0;
            row_list[cbase + __popc(bal & ((1u << lane) - 1u))] = tid;
        }
        __syncthreads();

        // warp w owns cols [w*256,(w+1)*256); lane owns 2x16B
        const ulonglong2* vec2 =
            reinterpret_cast<const ulonglong2*>(vec + (size_t)b * D);
        const ulonglong2 v0 = vec2[fbase];
        const ulonglong2 v1 = vec2[fbase + 32];

        float m = NEG_INF, z = 0.0f;
        ulonglong2 a0 = make_ulonglong2(0ull, 0ull);
        ulonglong2 a1 = make_ulonglong2(0ull, 0ull);

        const ulonglong2* sbase = reinterpret_cast<const ulonglong2*>(
            seq + ((size_t)b * L + row0) * D);
        const int nR = (n_rows + 7) >> 3;

        for (int rd = 0; rd < nR; rd++) {
            const int p    = rd & 1;
            const int idx0 = rd * 8;

            // front-batched: 16 streaming LDG.128 per warp
            ulonglong2 xa[8], xb[8];
#pragma unroll
            for (int r = 0; r < 8; r++) {
                const int ii = idx0 + r;
                const int rl = row_list[(ii < n_rows) ? ii : 0];
                const ulonglong2* s2 = sbase + (size_t)rl * (D / 4);
                xa[r] = ldcs_u2(s2 + fbase);
                xb[r] = ldcs_u2(s2 + fbase + 32);
            }

            // per-lane partial dots (f32x2)
            float pd[8];
#pragma unroll
            for (int r = 0; r < 8; r++) {
                unsigned long long d2 = f2mul(xa[r].x, v0.x);
                d2 = f2fma(xa[r].y, v0.y, d2);
                d2 = f2fma(xb[r].x, v1.x, d2);
                d2 = f2fma(xb[r].y, v1.y, d2);
                pd[r] = f2sum(d2);
            }

            // multi-value butterfly: fold rows offsets 1,2,4; finish 8,16
            float q[4];
#pragma unroll
            for (int i = 0; i < 4; i++) {
                const float keep = b0 ? pd[2 * i + 1] : pd[2 * i];
                const float send = b0 ? pd[2 * i]     : pd[2 * i + 1];
                q[i] = keep + __shfl_xor_sync(0xffffffffu, send, 1);
            }
            float r01, r23;
            {
                float keep = b1 ? q[1] : q[0];
                float send = b1 ? q[0] : q[1];
                r01 = keep + __shfl_xor_sync(0xffffffffu, send, 2);
                keep = b1 ? q[3] : q[2];
                send = b1 ? q[2] : q[3];
                r23 = keep + __shfl_xor_sync(0xffffffffu, send, 2);
            }
            float t;
            {
                const float keep = b2 ? r23 : r01;
                const float send = b2 ? r01 : r23;
                t = keep + __shfl_xor_sync(0xffffffffu, send, 4);
            }
            t += __shfl_xor_sync(0xffffffffu, t, 8);
            t += __shfl_xor_sync(0xffffffffu, t, 16);
            if (lane < 8) sp[p][lane][wid] = t;
            __syncthreads();

            // full dot for row = lane&7 (one LDS.128)
            const int row = lane & 7;
            const float4 sq =
                *reinterpret_cast<const float4*>(&sp[p][row][0]);
            const float dot = sq.x + sq.y + sq.z + sq.w;

            if (wid == 0 && lane < 8 && idx0 + lane < n_rows)
                g_scores[(size_t)b * L + row0 + row_list[idx0 + lane]] = dot;

            const float dv = (idx0 + row < n_rows) ? dot : NEG_INF;

            float rmax = dv;
            rmax = fmaxf(rmax, __shfl_xor_sync(0xffffffffu, rmax, 1));
            rmax = fmaxf(rmax, __shfl_xor_sync(0xffffffffu, rmax, 2));
            rmax = fmaxf(rmax, __shfl_xor_sync(0xffffffffu, rmax, 4));

            const float mnew  = fmaxf(m, rmax);
            const float scale = __expf(m - mnew);
            const float e     = __expf(dv - mnew);
            float es = e;
            es += __shfl_xor_sync(0xffffffffu, es, 1);
            es += __shfl_xor_sync(0xffffffffu, es, 2);
            es += __shfl_xor_sync(0xffffffffu, es, 4);
            z = z * scale + es;

            const unsigned long long s2v = f2bcast(scale);
            a0.x = f2mul(a0.x, s2v); a0.y = f2mul(a0.y, s2v);
            a1.x = f2mul(a1.x, s2v); a1.y = f2mul(a1.y, s2v);

#pragma unroll
            for (int r = 0; r < 8; r++) {
                const unsigned long long e2 =
                    f2bcast(__shfl_sync(0xffffffffu, e, r));
                a0.x = f2fma(xa[r].x, e2, a0.x);
                a0.y = f2fma(xa[r].y, e2, a0.y);
                a1.x = f2fma(xb[r].x, e2, a1.x);
                a1.y = f2fma(xb[r].y, e2, a1.y);
            }
            m = mnew;
        }

        // each warp writes its own slice; m,z identical across warps
        ulonglong2* pa = reinterpret_cast<ulonglong2*>(g_pacc[blk]);
        pa[fbase]      = a0;
        pa[fbase + 32] = a1;
        if (tid == 0) { g_pm[blk] = m; g_pz[blk] = z; }
        // loop-top __syncthreads protects row_list/sp reuse
    }
}

__global__ __launch_bounds__(THREADS2, 1)   // lifted reg cap -> MLP=8
void attn_pool_pass2(float* __restrict__ out_pooled,   // [B, D]
                     float* __restrict__ out_weights)  // [B, L]
{
    const int b    = blockIdx.x / P2_SPLIT;
    const int part = blockIdx.x % P2_SPLIT;
    const int tid  = threadIdx.x;

    if (blockIdx.x == 0 && tid == 0) g_next = 0;  // reset steal counter

    __shared__ float sh_sc[NCHUNK];
    __shared__ float sh_stats[2];
    __shared__ __align__(16) float4 sh_pool[8][32];

    // front-batch the pooled-partial loads FIRST (independent of stats)
    float4 t[NCHUNK / 8];
    {
        const int c4 = tid & 31;
        const int g  = tid >> 5;
#pragma unroll
        for (int jj = 0; jj < NCHUNK / 8; jj++) {
            const int j = g * (NCHUNK / 8) + jj;
            t[jj] = *reinterpret_cast<const float4*>(
                &g_pacc[b * NCHUNK + j][part * 128 + 4 * c4]);
        }
    }
    // weights scores load (also independent of stats)
    const int l0 = part * (L / P2_SPLIT) + tid * 2;
    const float2 sc2 =
        *reinterpret_cast<const float2*>(&g_scores[(size_t)b * L + l0]);

    if (tid < 32) {
        const float pa_m = g_pm[b * NCHUNK + tid];
        const float pb_m = g_pm[b * NCHUNK + tid + 32];
        float mloc = fmaxf(pa_m, pb_m);
#pragma unroll
        for (int o = 16; o > 0; o >>= 1)
            mloc = fmaxf(mloc, __shfl_xor_sync(0xffffffffu, mloc, o));
        const float s0 = __expf(pa_m - mloc);
        const float s1 = __expf(pb_m - mloc);
        sh_sc[tid]      = s0;
        sh_sc[tid + 32] = s1;
        float zl = g_pz[b * NCHUNK + tid] * s0
                 + g_pz[b * NCHUNK + tid + 32] * s1;
#pragma unroll
        for (int o = 16; o > 0; o >>= 1)
            zl += __shfl_xor_sync(0xffffffffu, zl, o);
        if (tid == 0) { sh_stats[0] = mloc; sh_stats[1] = 1.0f / zl; }
    }
    __syncthreads();
    const float m_f  = sh_stats[0];
    const float invZ = sh_stats[1];

    // pooled: weight the pre-loaded partials
    {
        const int c4 = tid & 31;
        const int g  = tid >> 5;
        float4 s = make_float4(0.f, 0.f, 0.f, 0.f);
#pragma unroll
        for (int jj = 0; jj < NCHUNK / 8; jj++) {
            const float w = sh_sc[g * (NCHUNK / 8) + jj];
            s.x += w * t[jj].x; s.y += w * t[jj].y;
            s.z += w * t[jj].z; s.w += w * t[jj].w;
        }
        sh_pool[g][c4] = s;
    }
    __syncthreads();
    if (tid < 32) {
        float4 s = sh_pool[0][tid];
#pragma unroll
        for (int g = 1; g < 8; g++) {
            const float4 u = sh_pool[g][tid];
            s.x += u.x; s.y += u.y; s.z += u.z; s.w += u.w;
        }
        s.x *= invZ; s.y *= invZ; s.z *= invZ; s.w *= invZ;
        reinterpret_cast<float4*>(out_pooled)[b * (D / 4) + part * 32 + tid] = s;
    }

    // weights from the pre-loaded scores
    {
        float2 w2;
        w2.x = __expf(sc2.x - m_f) * invZ;
        w2.y = __expf(sc2.y - m_f) * invZ;
        *reinterpret_cast<float2*>(&out_weights[(size_t)b * L + l0]) = w2;
    }
}

extern "C" void kernel_launch(void* const* d_in, const int* in_sizes, int n_in,
                              void* d_out, int out_size) {
    const float* seq  = (const float*)d_in[0];
    const float* vec  = (const float*)d_in[1];
    const int*   mask = (const int*)d_in[2];

    float* out_pooled  = (float*)d_out;               // [B, D]
    float* out_weights = out_pooled + (size_t)B * D;  // [B, L]

    attn_pool_pass1<<<GRID1, THREADS1>>>(seq, vec, mask);
    attn_pool_pass2<<<B * P2_SPLIT, THREADS2>>>(out_pooled, out_weights);
}

// round 17
// speedup vs baseline: 1.0439x; 1.0439x over previous
#include <cuda_runtime.h>
#include <cstdint>

#define NEG_INF (-1e30f)

constexpr int B = 32;
constexpr int L = 4096;
constexpr int D = 1024;

constexpr int THREADS1 = 128;
constexpr int WARPS1 = 4;
constexpr int ROWS_PER_BLOCK = 64;
constexpr int NCHUNK = L / ROWS_PER_BLOCK;   // 64
constexpr int NPART = B * NCHUNK;            // 2048

constexpr int P2_SPLIT = 8;                  // 128 cols per block
constexpr int THREADS2 = 256;

// Scratch (no allocations allowed in kernel_launch)
__device__ __align__(16) float g_scores[B * L];
__device__ __align__(16) float g_pacc[NPART][D];
__device__ float g_pm[NPART];
__device__ float g_pz[NPART];

// ---- packed f32x2 helpers (PTX-only; ptxas never emits FFMA2 from C++) ----
__device__ __forceinline__ unsigned long long f2fma(unsigned long long a,
                                                    unsigned long long b,
                                                    unsigned long long c) {
    unsigned long long d;
    asm("fma.rn.f32x2 %0, %1, %2, %3;" : "=l"(d) : "l"(a), "l"(b), "l"(c));
    return d;
}
__device__ __forceinline__ unsigned long long f2mul(unsigned long long a,
                                                    unsigned long long b) {
    unsigned long long d;
    asm("mul.rn.f32x2 %0, %1, %2;" : "=l"(d) : "l"(a), "l"(b));
    return d;
}
__device__ __forceinline__ float f2sum(unsigned long long a) {
    unsigned lo, hi;
    asm("mov.b64 {%0, %1}, %2;" : "=r"(lo), "=r"(hi) : "l"(a));
    return __uint_as_float(lo) + __uint_as_float(hi);
}
__device__ __forceinline__ unsigned long long f2bcast(float f) {
    unsigned long long d;
    unsigned u = __float_as_uint(f);
    asm("mov.b64 %0, {%1, %1};" : "=l"(d) : "r"(u));
    return d;
}
// streaming (evict-first) 16B load
__device__ __forceinline__ ulonglong2 ldcs_u2(const ulonglong2* p) {
    ulonglong2 r;
    asm volatile("ld.global.cs.v2.u64 {%0, %1}, [%2];"
                 : "=l"(r.x), "=l"(r.y) : "l"(p));
    return r;
}

__global__ __launch_bounds__(THREADS1, 5)
void attn_pool_pass1(const float* __restrict__ seq,
                     const float* __restrict__ vec,
                     const int*   __restrict__ mask) {
    const int blk   = blockIdx.x;
    const int b     = blk / NCHUNK;
    const int chunk = blk % NCHUNK;
    const int tid   = threadIdx.x;
    const int wid   = tid >> 5;
    const int lane  = tid & 31;
    const int row0  = chunk * ROWS_PER_BLOCK;

    __shared__ int row_list[ROWS_PER_BLOCK];
    __shared__ int cnt_sh[2];
    __shared__ __align__(16) float sp[2][8][4];   // [parity][row][warp]

    // ---- compaction of unmasked rows ----
    int mk = 0;
    if (tid < ROWS_PER_BLOCK)
        mk = mask[(size_t)b * L + row0 + tid];
    const unsigned bal = __ballot_sync(0xffffffffu, mk != 0);
    if (wid < 2 && lane == 0) cnt_sh[wid] = __popc(bal);
    if (tid < ROWS_PER_BLOCK && mk == 0)
        g_scores[(size_t)b * L + row0 + tid] = NEG_INF;
    __syncthreads();
    const int n_rows = cnt_sh[0] + cnt_sh[1];
    if (tid < ROWS_PER_BLOCK && mk != 0) {
        const int cbase = (wid == 1) ? cnt_sh[0] : 0;
        row_list[cbase + __popc(bal & ((1u << lane) - 1u))] = tid;
    }
    __syncthreads();

    // warp w owns cols [w*256,(w+1)*256); lane owns 2x16B (as u64 pairs)
    const int fbase = wid * 64 + lane;   // 16-byte-unit index within a row
    const ulonglong2* vec2 =
        reinterpret_cast<const ulonglong2*>(vec + (size_t)b * D);
    const ulonglong2 v0 = vec2[fbase];
    const ulonglong2 v1 = vec2[fbase + 32];

    float m = NEG_INF, z = 0.0f;
    ulonglong2 a0 = make_ulonglong2(0ull, 0ull);
    ulonglong2 a1 = make_ulonglong2(0ull, 0ull);

    const ulonglong2* sbase =
        reinterpret_cast<const ulonglong2*>(seq + ((size_t)b * L + row0) * D);
    const int nR = (n_rows + 7) >> 3;

    const unsigned b0 = lane & 1, b1 = (lane >> 1) & 1, b2 = (lane >> 2) & 1;

    for (int rd = 0; rd < nR; rd++) {
        const int p    = rd & 1;
        const int idx0 = rd * 8;

        // front-batched: 16 streaming LDG.128 per warp
        ulonglong2 xa[8], xb[8];
#pragma unroll
        for (int r = 0; r < 8; r++) {
            const int ii = idx0 + r;
            const int rl = row_list[(ii < n_rows) ? ii : 0];
            const ulonglong2* s2 = sbase + (size_t)rl * (D / 4);
            xa[r] = ldcs_u2(s2 + fbase);
            xb[r] = ldcs_u2(s2 + fbase + 32);
        }

        // per-lane partial dots (f32x2)
        float pd[8];
#pragma unroll
        for (int r = 0; r < 8; r++) {
            unsigned long long d2 = f2mul(xa[r].x, v0.x);
            d2 = f2fma(xa[r].y, v0.y, d2);
            d2 = f2fma(xb[r].x, v1.x, d2);
            d2 = f2fma(xb[r].y, v1.y, d2);
            pd[r] = f2sum(d2);
        }

        // multi-value butterfly: fold rows with offsets 1,2,4; finish 8,16
        float q[4];
#pragma unroll
        for (int i = 0; i < 4; i++) {
            const float keep = b0 ? pd[2 * i + 1] : pd[2 * i];
            const float send = b0 ? pd[2 * i]     : pd[2 * i + 1];
            q[i] = keep + __shfl_xor_sync(0xffffffffu, send, 1);
        }
        float r01, r23;
        {
            float keep = b1 ? q[1] : q[0];
            float send = b1 ? q[0] : q[1];
            r01 = keep + __shfl_xor_sync(0xffffffffu, send, 2);
            keep = b1 ? q[3] : q[2];
            send = b1 ? q[2] : q[3];
            r23 = keep + __shfl_xor_sync(0xffffffffu, send, 2);
        }
        float t;
        {
            const float keep = b2 ? r23 : r01;
            const float send = b2 ? r01 : r23;
            t = keep + __shfl_xor_sync(0xffffffffu, send, 4);
        }
        t += __shfl_xor_sync(0xffffffffu, t, 8);
        t += __shfl_xor_sync(0xffffffffu, t, 16);
        if (lane < 8) sp[p][lane][wid] = t;
        __syncthreads();

        // full dot for row = lane&7 (one LDS.128)
        const int row = lane & 7;
        const float4 sq = *reinterpret_cast<const float4*>(&sp[p][row][0]);
        const float dot = sq.x + sq.y + sq.z + sq.w;

        if (wid == 0 && lane < 8 && idx0 + lane < n_rows)
            g_scores[(size_t)b * L + row0 + row_list[idx0 + lane]] = dot;

        const float dv = (idx0 + row < n_rows) ? dot : NEG_INF;

        float rmax = dv;
        rmax = fmaxf(rmax, __shfl_xor_sync(0xffffffffu, rmax, 1));
        rmax = fmaxf(rmax, __shfl_xor_sync(0xffffffffu, rmax, 2));
        rmax = fmaxf(rmax, __shfl_xor_sync(0xffffffffu, rmax, 4));

        const float mnew  = fmaxf(m, rmax);
        const float scale = __expf(m - mnew);
        const float e     = __expf(dv - mnew);
        float es = e;
        es += __shfl_xor_sync(0xffffffffu, es, 1);
        es += __shfl_xor_sync(0xffffffffu, es, 2);
        es += __shfl_xor_sync(0xffffffffu, es, 4);
        z = z * scale + es;

        const unsigned long long s2v = f2bcast(scale);
        a0.x = f2mul(a0.x, s2v); a0.y = f2mul(a0.y, s2v);
        a1.x = f2mul(a1.x, s2v); a1.y = f2mul(a1.y, s2v);

#pragma unroll
        for (int r = 0; r < 8; r++) {
            const unsigned long long e2 =
                f2bcast(__shfl_sync(0xffffffffu, e, r));
            a0.x = f2fma(xa[r].x, e2, a0.x);
            a0.y = f2fma(xa[r].y, e2, a0.y);
            a1.x = f2fma(xb[r].x, e2, a1.x);
            a1.y = f2fma(xb[r].y, e2, a1.y);
        }
        m = mnew;
    }

    // each warp writes its own slice; m,z identical across warps
    ulonglong2* pa = reinterpret_cast<ulonglong2*>(g_pacc[blk]);
    pa[fbase]      = a0;
    pa[fbase + 32] = a1;
    if (tid == 0) { g_pm[blk] = m; g_pz[blk] = z; }

    // PDL: signal that this block's output is committed (dependency for the
    // programmatically-launched pass2 resolves when all blocks trigger/exit)
    cudaTriggerProgrammaticLaunchCompletion();
}

__global__ __launch_bounds__(THREADS2, 1)   // lifted reg cap -> MLP=8
void attn_pool_pass2(float* __restrict__ out_pooled,   // [B, D]
                     float* __restrict__ out_weights)  // [B, L]
{
    const int b    = blockIdx.x / P2_SPLIT;
    const int part = blockIdx.x % P2_SPLIT;
    const int tid  = threadIdx.x;

    __shared__ float sh_sc[NCHUNK];
    __shared__ float sh_stats[2];
    __shared__ __align__(16) float4 sh_pool[8][32];

    // preamble (overlaps pass1 tail under PDL): pure index math
    const int c4 = tid & 31;
    const int g  = tid >> 5;
    const int l0 = part * (L / P2_SPLIT) + tid * 2;

    // wait for pass1's grid to complete before touching its outputs
    cudaGridDependencySynchronize();

    // front-batch the pooled-partial loads FIRST (independent of stats)
    float4 t[NCHUNK / 8];
#pragma unroll
    for (int jj = 0; jj < NCHUNK / 8; jj++) {
        const int j = g * (NCHUNK / 8) + jj;
        t[jj] = *reinterpret_cast<const float4*>(
            &g_pacc[b * NCHUNK + j][part * 128 + 4 * c4]);
    }
    // weights scores load (also independent of stats)
    const float2 sc2 =
        *reinterpret_cast<const float2*>(&g_scores[(size_t)b * L + l0]);

    if (tid < 32) {
        const float pa_m = g_pm[b * NCHUNK + tid];
        const float pb_m = g_pm[b * NCHUNK + tid + 32];
        float mloc = fmaxf(pa_m, pb_m);
#pragma unroll
        for (int o = 16; o > 0; o >>= 1)
            mloc = fmaxf(mloc, __shfl_xor_sync(0xffffffffu, mloc, o));
        const float s0 = __expf(pa_m - mloc);
        const float s1 = __expf(pb_m - mloc);
        sh_sc[tid]      = s0;
        sh_sc[tid + 32] = s1;
        float zl = g_pz[b * NCHUNK + tid] * s0
                 + g_pz[b * NCHUNK + tid + 32] * s1;
#pragma unroll
        for (int o = 16; o > 0; o >>= 1)
            zl += __shfl_xor_sync(0xffffffffu, zl, o);
        if (tid == 0) { sh_stats[0] = mloc; sh_stats[1] = 1.0f / zl; }
    }
    __syncthreads();
    const float m_f  = sh_stats[0];
    const float invZ = sh_stats[1];

    // pooled: weight the pre-loaded partials
    {
        float4 s = make_float4(0.f, 0.f, 0.f, 0.f);
#pragma unroll
        for (int jj = 0; jj < NCHUNK / 8; jj++) {
            const float w = sh_sc[g * (NCHUNK / 8) + jj];
            s.x += w * t[jj].x; s.y += w * t[jj].y;
            s.z += w * t[jj].z; s.w += w * t[jj].w;
        }
        sh_pool[g][c4] = s;
    }
    __syncthreads();
    if (tid < 32) {
        float4 s = sh_pool[0][tid];
#pragma unroll
        for (int gg = 1; gg < 8; gg++) {
            const float4 u = sh_pool[gg][tid];
            s.x += u.x; s.y += u.y; s.z += u.z; s.w += u.w;
        }
        s.x *= invZ; s.y *= invZ; s.z *= invZ; s.w *= invZ;
        reinterpret_cast<float4*>(out_pooled)[b * (D / 4) + part * 32 + tid] = s;
    }

    // weights from the pre-loaded scores
    {
        float2 w2;
        w2.x = __expf(sc2.x - m_f) * invZ;
        w2.y = __expf(sc2.y - m_f) * invZ;
        *reinterpret_cast<float2*>(&out_weights[(size_t)b * L + l0]) = w2;
    }
}

extern "C" void kernel_launch(void* const* d_in, const int* in_sizes, int n_in,
                              void* d_out, int out_size) {
    const float* seq  = (const float*)d_in[0];
    const float* vec  = (const float*)d_in[1];
    const int*   mask = (const int*)d_in[2];

    float* out_pooled  = (float*)d_out;               // [B, D]
    float* out_weights = out_pooled + (size_t)B * D;  // [B, L]

    attn_pool_pass1<<<B * NCHUNK, THREADS1>>>(seq, vec, mask);

    // PDL launch: pass2 may be scheduled while pass1 drains; its
    // cudaGridDependencySynchronize() orders the data dependency.
    cudaLaunchConfig_t cfg = {};
    cfg.gridDim  = dim3(B * P2_SPLIT, 1, 1);
    cfg.blockDim = dim3(THREADS2, 1, 1);
    cfg.dynamicSmemBytes = 0;
    cfg.stream = 0;
    cudaLaunchAttribute attrs[1];
    attrs[0].id = cudaLaunchAttributeProgrammaticStreamSerialization;
    attrs[0].val.programmaticStreamSerializationAllowed = 1;
    cfg.attrs = attrs;
    cfg.numAttrs = 1;
    cudaLaunchKernelEx(&cfg, attn_pool_pass2, out_pooled, out_weights);
}